// round 1
// baseline (speedup 1.0000x reference)
#include <cuda_runtime.h>
#include <math.h>

// Problem constants
#define BB   4096              // batch
#define GG   4096              // genes (K of big GEMM)
#define NF   1536              // 64*24 flattened gene-layer outputs (N of big GEMM)
#define OUTC 86                // output columns: 64+16+4+1+1
#define EPSB 1e-5f

// ---------------- scratch (device globals; no allocation allowed) ----------
__device__ __align__(16) float g_hin[BB * NF];      // (B, 64, 24)
__device__ __align__(16) float g_h0[BB * 384];      // level0 z/h (B, 64, 6)
__device__ __align__(16) float g_h1[BB * 96];       // level1      (B, 16, 6)
__device__ __align__(16) float g_h2[BB * 24];       // level2      (B, 4, 6)
__device__ __align__(16) float g_h3[BB * 6];        // level3      (B, 1, 6)
__device__ __align__(16) float g_f [BB * 6];        // final tanh layer
__device__ float g_mean[512];
__device__ float g_var [512];

// ---------------------------------------------------------------------------
// Big GEMM: C[b,n] = sum_g x[b,g] * Wf[n,g] + bias[n]
// A = x (4096 x 4096, row-major), Wf = gene_W viewed (1536 x 4096, row-major)
// Tiles: BM=128 BN=128 BK=8, 256 threads, 8x8 microtile, double-buffered smem
// ---------------------------------------------------------------------------
#define BKT 8
#define NTILES (GG / BKT)   // 512

__global__ void __launch_bounds__(256)
sgemm_bias_kernel(const float* __restrict__ A, const float* __restrict__ Bw,
                  const float* __restrict__ bias, float* __restrict__ C) {
    __shared__ float As[2][BKT][132];
    __shared__ float Bs[2][BKT][132];

    const int tid = threadIdx.x;
    const int bm = blockIdx.y * 128;
    const int bn = blockIdx.x * 128;

    const int lrow = tid >> 1;          // 0..127
    const int lk   = (tid & 1) * 4;     // 0 or 4

    const float* Ap = A  + (size_t)(bm + lrow) * GG + lk;
    const float* Bp = Bw + (size_t)(bn + lrow) * GG + lk;

    const int ty = tid >> 4;            // 0..15
    const int tx = tid & 15;            // 0..15

    float acc[8][8];
#pragma unroll
    for (int i = 0; i < 8; i++)
#pragma unroll
        for (int j = 0; j < 8; j++) acc[i][j] = 0.0f;

    // preload tile 0
    {
        float4 av = *(const float4*)Ap;
        float4 bv = *(const float4*)Bp;
        As[0][lk + 0][lrow] = av.x; As[0][lk + 1][lrow] = av.y;
        As[0][lk + 2][lrow] = av.z; As[0][lk + 3][lrow] = av.w;
        Bs[0][lk + 0][lrow] = bv.x; Bs[0][lk + 1][lrow] = bv.y;
        Bs[0][lk + 2][lrow] = bv.z; Bs[0][lk + 3][lrow] = bv.w;
    }
    __syncthreads();

    for (int t = 0; t < NTILES; ++t) {
        const int cur = t & 1, nxt = cur ^ 1;
        float4 av, bv;
        const bool more = (t + 1 < NTILES);
        if (more) {
            av = *(const float4*)(Ap + (size_t)(t + 1) * BKT);
            bv = *(const float4*)(Bp + (size_t)(t + 1) * BKT);
        }
#pragma unroll
        for (int k = 0; k < BKT; ++k) {
            float a[8], b[8];
            *(float4*)(a)     = *(const float4*)&As[cur][k][ty * 8];
            *(float4*)(a + 4) = *(const float4*)&As[cur][k][ty * 8 + 4];
            *(float4*)(b)     = *(const float4*)&Bs[cur][k][tx * 8];
            *(float4*)(b + 4) = *(const float4*)&Bs[cur][k][tx * 8 + 4];
#pragma unroll
            for (int i = 0; i < 8; i++)
#pragma unroll
                for (int j = 0; j < 8; j++)
                    acc[i][j] = fmaf(a[i], b[j], acc[i][j]);
        }
        if (more) {
            As[nxt][lk + 0][lrow] = av.x; As[nxt][lk + 1][lrow] = av.y;
            As[nxt][lk + 2][lrow] = av.z; As[nxt][lk + 3][lrow] = av.w;
            Bs[nxt][lk + 0][lrow] = bv.x; Bs[nxt][lk + 1][lrow] = bv.y;
            Bs[nxt][lk + 2][lrow] = bv.z; Bs[nxt][lk + 3][lrow] = bv.w;
        }
        __syncthreads();
    }

    float bcol[8];
#pragma unroll
    for (int j = 0; j < 8; j++) bcol[j] = bias[bn + tx * 8 + j];

#pragma unroll
    for (int i = 0; i < 8; i++) {
        const int row = bm + ty * 8 + i;
        float4 v0, v1;
        v0.x = acc[i][0] + bcol[0]; v0.y = acc[i][1] + bcol[1];
        v0.z = acc[i][2] + bcol[2]; v0.w = acc[i][3] + bcol[3];
        v1.x = acc[i][4] + bcol[4]; v1.y = acc[i][5] + bcol[5];
        v1.z = acc[i][6] + bcol[6]; v1.w = acc[i][7] + bcol[7];
        *(float4*)&C[(size_t)row * NF + bn + tx * 8 + 0] = v0;
        *(float4*)&C[(size_t)row * NF + bn + tx * 8 + 4] = v1;
    }
}

// ---------------------------------------------------------------------------
// Term layer: z[b, t*6+h] = tanh( dot(in[b, t*24 .. +24], W[off+t, h, :]) + b )
// grid = (B/256, n); uniform input width 24 for all levels.
// ---------------------------------------------------------------------------
__global__ void __launch_bounds__(256)
term_kernel(const float* __restrict__ in, int inStride,
            const float* __restrict__ termW, const float* __restrict__ termb,
            int off, int n, float* __restrict__ z) {
    const int t = blockIdx.y;
    __shared__ float Ws[144];
    __shared__ float bs[6];
    if (threadIdx.x < 144) Ws[threadIdx.x] = termW[(size_t)(off + t) * 144 + threadIdx.x];
    if (threadIdx.x < 6)   bs[threadIdx.x] = termb[(size_t)(off + t) * 6 + threadIdx.x];
    __syncthreads();

    const int b = blockIdx.x * blockDim.x + threadIdx.x;
    if (b >= BB) return;

    float xin[24];
    const float* ip = in + (size_t)b * inStride + t * 24;
#pragma unroll
    for (int i = 0; i < 24; i += 4) *(float4*)&xin[i] = *(const float4*)&ip[i];

    const int C = n * 6;
#pragma unroll
    for (int h = 0; h < 6; h++) {
        float s = bs[h];
#pragma unroll
        for (int i = 0; i < 24; i++) s = fmaf(xin[i], Ws[h * 24 + i], s);
        z[(size_t)b * C + t * 6 + h] = tanhf(s);
    }
}

// ---------------------------------------------------------------------------
// Batch-norm stats: per channel c (over B). block = (32, 8), grid = ceil(C/32)
// fp64 accumulation for robust mean/var.
// ---------------------------------------------------------------------------
__global__ void stats_kernel(const float* __restrict__ z, int C) {
    const int c = blockIdx.x * 32 + threadIdx.x;
    const int ty = threadIdx.y;
    double s = 0.0, sq = 0.0;
    if (c < C) {
        for (int b = ty; b < BB; b += 8) {
            float v = z[(size_t)b * C + c];
            s += v;
            sq += (double)v * v;
        }
    }
    __shared__ double sh_s[8][33];
    __shared__ double sh_q[8][33];
    sh_s[ty][threadIdx.x] = s;
    sh_q[ty][threadIdx.x] = sq;
    __syncthreads();
    if (ty == 0 && c < C) {
#pragma unroll
        for (int r = 1; r < 8; r++) { s += sh_s[r][threadIdx.x]; sq += sh_q[r][threadIdx.x]; }
        float mu = (float)(s / (double)BB);
        g_mean[c] = mu;
        g_var[c]  = (float)(sq / (double)BB - (double)mu * (double)mu);
    }
}

// ---------------------------------------------------------------------------
// Normalize (in place) + aux heads -> output column
// ---------------------------------------------------------------------------
__global__ void __launch_bounds__(256)
bnaux_kernel(float* __restrict__ zh,
             const float* __restrict__ gamma, const float* __restrict__ beta,
             const float* __restrict__ a1W, const float* __restrict__ a1b,
             const float* __restrict__ a2W, const float* __restrict__ a2b,
             int off, int n, int colOff, float* __restrict__ out) {
    const int t = blockIdx.y;
    const int b = blockIdx.x * blockDim.x + threadIdx.x;
    if (b >= BB) return;
    const int C = n * 6;
    float a = a1b[off + t];
#pragma unroll
    for (int k = 0; k < 6; k++) {
        const int c = t * 6 + k;
        float v = zh[(size_t)b * C + c];
        float hv = (v - g_mean[c]) * rsqrtf(g_var[c] + EPSB) * gamma[(size_t)(off + t) * 6 + k]
                   + beta[(size_t)(off + t) * 6 + k];
        zh[(size_t)b * C + c] = hv;
        a = fmaf(hv, a1W[(size_t)(off + t) * 6 + k], a);
    }
    float a1 = tanhf(a);
    out[(size_t)b * OUTC + colOff + t] = fmaf(a1, a2W[off + t], a2b[off + t]);
}

// ---------------------------------------------------------------------------
// Final head part 1: f = tanh(root @ final_W^T + final_b)
// ---------------------------------------------------------------------------
__global__ void __launch_bounds__(256)
final1_kernel(const float* __restrict__ fW, const float* __restrict__ fb) {
    const int b = blockIdx.x * blockDim.x + threadIdx.x;
    if (b >= BB) return;
    float r[6];
#pragma unroll
    for (int i = 0; i < 6; i++) r[i] = g_h3[(size_t)b * 6 + i];
#pragma unroll
    for (int o = 0; o < 6; o++) {
        float s = fb[o];
#pragma unroll
        for (int i = 0; i < 6; i++) s = fmaf(r[i], fW[o * 6 + i], s);
        g_f[(size_t)b * 6 + o] = tanhf(s);
    }
}

// ---------------------------------------------------------------------------
// Final head part 2: BN(f) -> faux tanh -> sigmoid -> out col 85
// ---------------------------------------------------------------------------
__global__ void __launch_bounds__(256)
final2_kernel(const float* __restrict__ fg, const float* __restrict__ fbta,
              const float* __restrict__ fauxW, const float* __restrict__ fauxb,
              const float* __restrict__ foutW, const float* __restrict__ foutb,
              float* __restrict__ out) {
    const int b = blockIdx.x * blockDim.x + threadIdx.x;
    if (b >= BB) return;
    float a = fauxb[0];
#pragma unroll
    for (int h = 0; h < 6; h++) {
        float v = (g_f[(size_t)b * 6 + h] - g_mean[h]) * rsqrtf(g_var[h] + EPSB) * fg[h] + fbta[h];
        a = fmaf(v, fauxW[h], a);
    }
    float fa = tanhf(a);
    float p = fmaf(fa, foutW[0], foutb[0]);
    out[(size_t)b * OUTC + 85] = 1.0f / (1.0f + expf(-p));
}

// ---------------------------------------------------------------------------
extern "C" void kernel_launch(void* const* d_in, const int* in_sizes, int n_in,
                              void* d_out, int out_size) {
    (void)in_sizes; (void)n_in; (void)out_size;
    const float* x      = (const float*)d_in[0];
    const float* geneW  = (const float*)d_in[1];
    const float* geneb  = (const float*)d_in[2];
    const float* termW  = (const float*)d_in[3];
    const float* termb  = (const float*)d_in[4];
    const float* bng    = (const float*)d_in[5];
    const float* bnb    = (const float*)d_in[6];
    const float* a1W    = (const float*)d_in[7];
    const float* a1b    = (const float*)d_in[8];
    const float* a2W    = (const float*)d_in[9];
    const float* a2b    = (const float*)d_in[10];
    const float* finalW = (const float*)d_in[11];
    const float* finalb = (const float*)d_in[12];
    const float* fbng   = (const float*)d_in[13];
    const float* fbnb   = (const float*)d_in[14];
    const float* fauxW  = (const float*)d_in[15];
    const float* fauxb  = (const float*)d_in[16];
    const float* foutW  = (const float*)d_in[17];
    const float* foutb  = (const float*)d_in[18];
    float* out = (float*)d_out;

    float *hin, *h0, *h1, *h2, *h3, *f;
    cudaGetSymbolAddress((void**)&hin, g_hin);
    cudaGetSymbolAddress((void**)&h0, g_h0);
    cudaGetSymbolAddress((void**)&h1, g_h1);
    cudaGetSymbolAddress((void**)&h2, g_h2);
    cudaGetSymbolAddress((void**)&h3, g_h3);
    cudaGetSymbolAddress((void**)&f, g_f);

    // 1) gene layer GEMM: (4096x4096) @ (1536x4096)^T + bias
    {
        dim3 grid(NF / 128, BB / 128);
        sgemm_bias_kernel<<<grid, 256>>>(x, geneW, geneb, hin);
    }

    const int   lvl_n[4]      = {64, 16, 4, 1};
    const int   lvl_off[4]    = {0, 64, 80, 84};
    const int   lvl_col[4]    = {0, 64, 80, 84};
    const int   lvl_inStride[4] = {NF, 384, 96, 24};
    const float* lvl_in[4]    = {hin, h0, h1, h2};
    float*      lvl_z[4]      = {h0, h1, h2, h3};

    for (int l = 0; l < 4; l++) {
        const int n = lvl_n[l], off = lvl_off[l];
        const int C = n * 6;
        dim3 gterm(BB / 256, n);
        term_kernel<<<gterm, 256>>>(lvl_in[l], lvl_inStride[l], termW, termb, off, n, lvl_z[l]);
        dim3 gstat((C + 31) / 32);
        stats_kernel<<<gstat, dim3(32, 8)>>>(lvl_z[l], C);
        bnaux_kernel<<<gterm, 256>>>(lvl_z[l], bng, bnb, a1W, a1b, a2W, a2b,
                                     off, n, lvl_col[l], out);
    }

    // final head
    final1_kernel<<<BB / 256, 256>>>(finalW, finalb);
    stats_kernel<<<1, dim3(32, 8)>>>(f, 6);
    final2_kernel<<<BB / 256, 256>>>(fbng, fbnb, fauxW, fauxb, foutW, foutb, out);
}

// round 3
// speedup vs baseline: 2.2489x; 2.2489x over previous
#include <cuda_runtime.h>
#include <cuda_bf16.h>
#include <math.h>
#include <stdint.h>

// Problem constants
#define BB   4096
#define GG   4096
#define NF   1536
#define OUTC 86
#define EPSB 1e-5f

// ---------------- scratch (device globals; no allocation allowed) ----------
__device__ __align__(16) float g_hin[BB * NF];
__device__ __align__(16) float g_h0[BB * 384];
__device__ __align__(16) float g_h1[BB * 96];
__device__ __align__(16) float g_h2[BB * 24];
__device__ __align__(16) float g_h3[BB * 6];
__device__ __align__(16) float g_f [BB * 6];
__device__ float g_mean[512];
__device__ float g_var [512];
__device__ __align__(16) __nv_bfloat16 g_xhi[BB * GG];
__device__ __align__(16) __nv_bfloat16 g_xlo[BB * GG];
__device__ __align__(16) __nv_bfloat16 g_whi[NF * GG];
__device__ __align__(16) __nv_bfloat16 g_wlo[NF * GG];

// ======================= helpers ===========================================
__device__ __forceinline__ uint32_t smem_u32(const void* p) {
    uint32_t a;
    asm("{ .reg .u64 t; cvta.to.shared.u64 t, %1; cvt.u32.u64 %0, t; }" : "=r"(a) : "l"(p));
    return a;
}
#define CPA16(dst, src) \
    asm volatile("cp.async.cg.shared.global [%0], [%1], 16;" :: "r"(dst), "l"(src))
#define CPA_COMMIT() asm volatile("cp.async.commit_group;" ::: "memory")

#define LDSM4(r, addr) \
    asm volatile("ldmatrix.sync.aligned.m8n8.x4.shared.b16 {%0,%1,%2,%3}, [%4];" \
                 : "=r"((r)[0]), "=r"((r)[1]), "=r"((r)[2]), "=r"((r)[3]) : "r"(addr))
#define LDSM2(r, addr) \
    asm volatile("ldmatrix.sync.aligned.m8n8.x2.shared.b16 {%0,%1}, [%2];" \
                 : "=r"((r)[0]), "=r"((r)[1]) : "r"(addr))

__device__ __forceinline__ void mma_bf16(float* d, const uint32_t* a, const uint32_t* b) {
    asm volatile(
        "mma.sync.aligned.m16n8k16.row.col.f32.bf16.bf16.f32 "
        "{%0,%1,%2,%3}, {%4,%5,%6,%7}, {%8,%9}, {%0,%1,%2,%3};"
        : "+f"(d[0]), "+f"(d[1]), "+f"(d[2]), "+f"(d[3])
        : "r"(a[0]), "r"(a[1]), "r"(a[2]), "r"(a[3]), "r"(b[0]), "r"(b[1]));
}

// ======================= fp32 -> bf16 hi/lo split ==========================
__global__ void __launch_bounds__(256)
split_kernel(const float* __restrict__ src, __nv_bfloat16* __restrict__ hi,
             __nv_bfloat16* __restrict__ lo, int n4) {
    int i = blockIdx.x * blockDim.x + threadIdx.x;
    if (i >= n4) return;
    float4 v = ((const float4*)src)[i];
    __nv_bfloat16 h0 = __float2bfloat16(v.x), h1 = __float2bfloat16(v.y);
    __nv_bfloat16 h2 = __float2bfloat16(v.z), h3 = __float2bfloat16(v.w);
    __nv_bfloat16 l0 = __float2bfloat16(v.x - __bfloat162float(h0));
    __nv_bfloat16 l1 = __float2bfloat16(v.y - __bfloat162float(h1));
    __nv_bfloat16 l2 = __float2bfloat16(v.z - __bfloat162float(h2));
    __nv_bfloat16 l3 = __float2bfloat16(v.w - __bfloat162float(h3));
    ((__nv_bfloat162*)hi)[i * 2 + 0] = __nv_bfloat162{h0, h1};
    ((__nv_bfloat162*)hi)[i * 2 + 1] = __nv_bfloat162{h2, h3};
    ((__nv_bfloat162*)lo)[i * 2 + 0] = __nv_bfloat162{l0, l1};
    ((__nv_bfloat162*)lo)[i * 2 + 1] = __nv_bfloat162{l2, l3};
}

// ======================= bf16 mma.sync GEMM ================================
// C[m,n] = sum_k (Ahi+Alo)[m,k]*(Bhi+Blo)[n,k] + bias[n]  (drop lo*lo)
// CTA tile 128x128, K-chunk 64, 8 warps (warp tile 64x32), 2-stage cp.async.
#define KCH     64
#define NCHUNK  (GG / KCH)        // 64
#define ROWB    144               // padded row stride (bytes) for 64 bf16
#define MAT_B   (128 * ROWB)      // 18432 bytes per 128x64 tile
#define A_HI_O  0
#define A_LO_O  (1 * MAT_B)
#define B_HI_O  (2 * MAT_B)
#define B_LO_O  (3 * MAT_B)
#define STAGE_B (4 * MAT_B)       // 73728
#define GEMM_SMEM (2 * STAGE_B)   // 147456

__global__ void __launch_bounds__(256, 1)
gemm_mma_kernel(const __nv_bfloat16* __restrict__ Ahi, const __nv_bfloat16* __restrict__ Alo,
                const __nv_bfloat16* __restrict__ Bhi, const __nv_bfloat16* __restrict__ Blo,
                const float* __restrict__ bias, float* __restrict__ C) {
    extern __shared__ __align__(128) char smem[];
    const uint32_t sb = smem_u32(smem);
    const int tid  = threadIdx.x;
    const int wid  = tid >> 5, lane = tid & 31;
    const int wm   = wid & 1;          // 0..1  -> 64-row block
    const int wn   = wid >> 1;         // 0..3  -> 32-col block
    const int m0   = blockIdx.y * 128, n0 = blockIdx.x * 128;

    const __nv_bfloat16* pA0 = Ahi + (size_t)m0 * GG;
    const __nv_bfloat16* pA1 = Alo + (size_t)m0 * GG;
    const __nv_bfloat16* pB0 = Bhi + (size_t)n0 * GG;
    const __nv_bfloat16* pB1 = Blo + (size_t)n0 * GG;

    float acc[4][4][4];
#pragma unroll
    for (int i = 0; i < 4; i++)
#pragma unroll
        for (int j = 0; j < 4; j++)
#pragma unroll
            for (int r = 0; r < 4; r++) acc[i][j][r] = 0.0f;

    // per-lane ldmatrix base offsets (within a matrix tile)
    const uint32_t aOff = (uint32_t)(wm * 64 + (lane & 15)) * ROWB + (uint32_t)(lane >> 4) * 16;
    const int bl = lane & 15;
    const uint32_t bOff = (uint32_t)(wn * 32 + (bl & 7)) * ROWB + (uint32_t)((bl >> 3) & 1) * 16;

    // chunk loader: 4 matrices x 1024 x 16B cp.async
    auto load_chunk = [&](int u, int s) {
        const uint32_t stb = sb + (uint32_t)s * STAGE_B;
        const size_t kof = (size_t)u * KCH;
#pragma unroll
        for (int j = 0; j < 4; ++j) {
            const int idx = tid + j * 256;
            const int row = idx >> 3, ch = idx & 7;
            const uint32_t so = (uint32_t)row * ROWB + (uint32_t)ch * 16;
            const size_t go = (size_t)row * GG + kof + (size_t)ch * 8;
            CPA16(stb + A_HI_O + so, pA0 + go);
            CPA16(stb + A_LO_O + so, pA1 + go);
            CPA16(stb + B_HI_O + so, pB0 + go);
            CPA16(stb + B_LO_O + so, pB1 + go);
        }
        CPA_COMMIT();
    };

    load_chunk(0, 0);

    for (int t = 0; t < NCHUNK; ++t) {
        if (t + 1 < NCHUNK) load_chunk(t + 1, (t + 1) & 1);
        if (t + 1 < NCHUNK) { asm volatile("cp.async.wait_group 1;" ::: "memory"); }
        else                { asm volatile("cp.async.wait_group 0;" ::: "memory"); }
        __syncthreads();

        const uint32_t stb = sb + (uint32_t)(t & 1) * STAGE_B;
        const uint32_t aHi = stb + A_HI_O + aOff;
        const uint32_t aLo = stb + A_LO_O + aOff;
        const uint32_t bHi = stb + B_HI_O + bOff;
        const uint32_t bLo = stb + B_LO_O + bOff;

#pragma unroll
        for (int ks = 0; ks < 4; ++ks) {
            uint32_t ah[4][4], al[4][4], bh[4][2], blr[4][2];
#pragma unroll
            for (int mi = 0; mi < 4; ++mi) {
                LDSM4(ah[mi], aHi + (uint32_t)mi * 16 * ROWB + (uint32_t)ks * 32);
                LDSM4(al[mi], aLo + (uint32_t)mi * 16 * ROWB + (uint32_t)ks * 32);
            }
#pragma unroll
            for (int ni = 0; ni < 4; ++ni) {
                LDSM2(bh[ni],  bHi + (uint32_t)ni * 8 * ROWB + (uint32_t)ks * 32);
                LDSM2(blr[ni], bLo + (uint32_t)ni * 8 * ROWB + (uint32_t)ks * 32);
            }
#pragma unroll
            for (int mi = 0; mi < 4; ++mi)
#pragma unroll
                for (int ni = 0; ni < 4; ++ni) {
                    mma_bf16(acc[mi][ni], ah[mi], bh[ni]);
                    mma_bf16(acc[mi][ni], ah[mi], blr[ni]);
                    mma_bf16(acc[mi][ni], al[mi], bh[ni]);
                }
        }
        __syncthreads();
    }

    // epilogue: D layout m16n8 -> rows lane/4 (+8), cols (lane%4)*2
    const int rbase = m0 + wm * 64 + (lane >> 2);
    const int cbase = n0 + wn * 32 + (lane & 3) * 2;
#pragma unroll
    for (int mi = 0; mi < 4; ++mi) {
#pragma unroll
        for (int ni = 0; ni < 4; ++ni) {
            const int col = cbase + ni * 8;
            const float b0 = __ldg(&bias[col]), b1 = __ldg(&bias[col + 1]);
            const int r0 = rbase + mi * 16;
            float2 v0 = make_float2(acc[mi][ni][0] + b0, acc[mi][ni][1] + b1);
            float2 v1 = make_float2(acc[mi][ni][2] + b0, acc[mi][ni][3] + b1);
            *(float2*)&C[(size_t)r0 * NF + col]       = v0;
            *(float2*)&C[(size_t)(r0 + 8) * NF + col] = v1;
        }
    }
}

// ======================= downstream (unchanged, passing) ===================
__global__ void __launch_bounds__(256)
term_kernel(const float* __restrict__ in, int inStride,
            const float* __restrict__ termW, const float* __restrict__ termb,
            int off, int n, float* __restrict__ z) {
    const int t = blockIdx.y;
    __shared__ float Ws[144];
    __shared__ float bs[6];
    if (threadIdx.x < 144) Ws[threadIdx.x] = termW[(size_t)(off + t) * 144 + threadIdx.x];
    if (threadIdx.x < 6)   bs[threadIdx.x] = termb[(size_t)(off + t) * 6 + threadIdx.x];
    __syncthreads();
    const int b = blockIdx.x * blockDim.x + threadIdx.x;
    if (b >= BB) return;
    float xin[24];
    const float* ip = in + (size_t)b * inStride + t * 24;
#pragma unroll
    for (int i = 0; i < 24; i += 4) *(float4*)&xin[i] = *(const float4*)&ip[i];
    const int C = n * 6;
#pragma unroll
    for (int h = 0; h < 6; h++) {
        float s = bs[h];
#pragma unroll
        for (int i = 0; i < 24; i++) s = fmaf(xin[i], Ws[h * 24 + i], s);
        z[(size_t)b * C + t * 6 + h] = tanhf(s);
    }
}

__global__ void stats_kernel(const float* __restrict__ z, int C) {
    const int c = blockIdx.x * 32 + threadIdx.x;
    const int ty = threadIdx.y;
    double s = 0.0, sq = 0.0;
    if (c < C) {
        for (int b = ty; b < BB; b += 8) {
            float v = z[(size_t)b * C + c];
            s += v;
            sq += (double)v * v;
        }
    }
    __shared__ double sh_s[8][33];
    __shared__ double sh_q[8][33];
    sh_s[ty][threadIdx.x] = s;
    sh_q[ty][threadIdx.x] = sq;
    __syncthreads();
    if (ty == 0 && c < C) {
#pragma unroll
        for (int r = 1; r < 8; r++) { s += sh_s[r][threadIdx.x]; sq += sh_q[r][threadIdx.x]; }
        float mu = (float)(s / (double)BB);
        g_mean[c] = mu;
        g_var[c]  = (float)(sq / (double)BB - (double)mu * (double)mu);
    }
}

__global__ void __launch_bounds__(256)
bnaux_kernel(float* __restrict__ zh,
             const float* __restrict__ gamma, const float* __restrict__ beta,
             const float* __restrict__ a1W, const float* __restrict__ a1b,
             const float* __restrict__ a2W, const float* __restrict__ a2b,
             int off, int n, int colOff, float* __restrict__ out) {
    const int t = blockIdx.y;
    const int b = blockIdx.x * blockDim.x + threadIdx.x;
    if (b >= BB) return;
    const int C = n * 6;
    float a = a1b[off + t];
#pragma unroll
    for (int k = 0; k < 6; k++) {
        const int c = t * 6 + k;
        float v = zh[(size_t)b * C + c];
        float hv = (v - g_mean[c]) * rsqrtf(g_var[c] + EPSB) * gamma[(size_t)(off + t) * 6 + k]
                   + beta[(size_t)(off + t) * 6 + k];
        zh[(size_t)b * C + c] = hv;
        a = fmaf(hv, a1W[(size_t)(off + t) * 6 + k], a);
    }
    float a1 = tanhf(a);
    out[(size_t)b * OUTC + colOff + t] = fmaf(a1, a2W[off + t], a2b[off + t]);
}

__global__ void __launch_bounds__(256)
final1_kernel(const float* __restrict__ fW, const float* __restrict__ fb) {
    const int b = blockIdx.x * blockDim.x + threadIdx.x;
    if (b >= BB) return;
    float r[6];
#pragma unroll
    for (int i = 0; i < 6; i++) r[i] = g_h3[(size_t)b * 6 + i];
#pragma unroll
    for (int o = 0; o < 6; o++) {
        float s = fb[o];
#pragma unroll
        for (int i = 0; i < 6; i++) s = fmaf(r[i], fW[o * 6 + i], s);
        g_f[(size_t)b * 6 + o] = tanhf(s);
    }
}

__global__ void __launch_bounds__(256)
final2_kernel(const float* __restrict__ fg, const float* __restrict__ fbta,
              const float* __restrict__ fauxW, const float* __restrict__ fauxb,
              const float* __restrict__ foutW, const float* __restrict__ foutb,
              float* __restrict__ out) {
    const int b = blockIdx.x * blockDim.x + threadIdx.x;
    if (b >= BB) return;
    float a = fauxb[0];
#pragma unroll
    for (int h = 0; h < 6; h++) {
        float v = (g_f[(size_t)b * 6 + h] - g_mean[h]) * rsqrtf(g_var[h] + EPSB) * fg[h] + fbta[h];
        a = fmaf(v, fauxW[h], a);
    }
    float fa = tanhf(a);
    float p = fmaf(fa, foutW[0], foutb[0]);
    out[(size_t)b * OUTC + 85] = 1.0f / (1.0f + expf(-p));
}

// ---------------------------------------------------------------------------
extern "C" void kernel_launch(void* const* d_in, const int* in_sizes, int n_in,
                              void* d_out, int out_size) {
    (void)in_sizes; (void)n_in; (void)out_size;
    const float* x      = (const float*)d_in[0];
    const float* geneW  = (const float*)d_in[1];
    const float* geneb  = (const float*)d_in[2];
    const float* termW  = (const float*)d_in[3];
    const float* termb  = (const float*)d_in[4];
    const float* bng    = (const float*)d_in[5];
    const float* bnb    = (const float*)d_in[6];
    const float* a1W    = (const float*)d_in[7];
    const float* a1b    = (const float*)d_in[8];
    const float* a2W    = (const float*)d_in[9];
    const float* a2b    = (const float*)d_in[10];
    const float* finalW = (const float*)d_in[11];
    const float* finalb = (const float*)d_in[12];
    const float* fbng   = (const float*)d_in[13];
    const float* fbnb   = (const float*)d_in[14];
    const float* fauxW  = (const float*)d_in[15];
    const float* fauxb  = (const float*)d_in[16];
    const float* foutW  = (const float*)d_in[17];
    const float* foutb  = (const float*)d_in[18];
    float* out = (float*)d_out;

    float *hin, *h0, *h1, *h2, *h3, *f;
    __nv_bfloat16 *xhi, *xlo, *whi, *wlo;
    cudaGetSymbolAddress((void**)&hin, g_hin);
    cudaGetSymbolAddress((void**)&h0, g_h0);
    cudaGetSymbolAddress((void**)&h1, g_h1);
    cudaGetSymbolAddress((void**)&h2, g_h2);
    cudaGetSymbolAddress((void**)&h3, g_h3);
    cudaGetSymbolAddress((void**)&f, g_f);
    cudaGetSymbolAddress((void**)&xhi, g_xhi);
    cudaGetSymbolAddress((void**)&xlo, g_xlo);
    cudaGetSymbolAddress((void**)&whi, g_whi);
    cudaGetSymbolAddress((void**)&wlo, g_wlo);

    // 0) split fp32 -> bf16 hi/lo
    split_kernel<<<(BB * GG / 4 + 255) / 256, 256>>>(x, xhi, xlo, BB * GG / 4);
    split_kernel<<<(NF * GG / 4 + 255) / 256, 256>>>(geneW, whi, wlo, NF * GG / 4);

    // 1) gene layer GEMM via mma.sync bf16 (3-pass hi/lo)
    {
        static bool attr_set = false;
        if (!attr_set) {
            cudaFuncSetAttribute(gemm_mma_kernel,
                                 cudaFuncAttributeMaxDynamicSharedMemorySize, GEMM_SMEM);
            attr_set = true;
        }
        dim3 grid(NF / 128, BB / 128);
        gemm_mma_kernel<<<grid, 256, GEMM_SMEM>>>(xhi, xlo, whi, wlo, geneb, hin);
    }

    const int   lvl_n[4]        = {64, 16, 4, 1};
    const int   lvl_off[4]      = {0, 64, 80, 84};
    const int   lvl_inStride[4] = {NF, 384, 96, 24};
    const float* lvl_in[4]      = {hin, h0, h1, h2};
    float*      lvl_z[4]        = {h0, h1, h2, h3};

    for (int l = 0; l < 4; l++) {
        const int n = lvl_n[l], off = lvl_off[l];
        const int C = n * 6;
        dim3 gterm(BB / 256, n);
        term_kernel<<<gterm, 256>>>(lvl_in[l], lvl_inStride[l], termW, termb, off, n, lvl_z[l]);
        dim3 gstat((C + 31) / 32);
        stats_kernel<<<gstat, dim3(32, 8)>>>(lvl_z[l], C);
        bnaux_kernel<<<gterm, 256>>>(lvl_z[l], bng, bnb, a1W, a1b, a2W, a2b,
                                     off, n, off, out);
    }

    final1_kernel<<<BB / 256, 256>>>(finalW, finalb);
    stats_kernel<<<1, dim3(32, 8)>>>(f, 6);
    final2_kernel<<<BB / 256, 256>>>(fbng, fbnb, fauxW, fauxb, foutW, foutb, out);
}

// round 5
// speedup vs baseline: 2.3579x; 1.0485x over previous
#include <cuda_runtime.h>
#include <cuda_bf16.h>
#include <math.h>
#include <stdint.h>

// Problem constants
#define BB   4096
#define GG   4096
#define NF   1536
#define OUTC 86
#define EPSB 1e-5f

// ---------------- scratch (device globals) ---------------------------------
__device__ __align__(16) float g_hin[BB * NF];
__device__ __align__(16) float g_h0[BB * 384];
__device__ __align__(16) float g_h1[BB * 96];
__device__ __align__(16) float g_h2[BB * 24];
__device__ __align__(16) float g_h3[BB * 6];
__device__ __align__(16) float g_f [BB * 6];
__device__ float g_mean[512];
__device__ float g_var [512];
__device__ __align__(16) __nv_bfloat16 g_xhi[BB * GG];
__device__ __align__(16) __nv_bfloat16 g_xlo[BB * GG];
__device__ __align__(16) __nv_bfloat16 g_whi[NF * GG];
__device__ __align__(16) __nv_bfloat16 g_wlo[NF * GG];

// ======================= helpers ===========================================
__device__ __forceinline__ uint32_t smem_u32(const void* p) {
    uint32_t a;
    asm("{ .reg .u64 t; cvta.to.shared.u64 t, %1; cvt.u32.u64 %0, t; }" : "=r"(a) : "l"(p));
    return a;
}
#define CPA16(dst, src) \
    asm volatile("cp.async.cg.shared.global [%0], [%1], 16;" :: "r"(dst), "l"(src))
#define CPA_COMMIT() asm volatile("cp.async.commit_group;" ::: "memory")

#define LDSM4(r, addr) \
    asm volatile("ldmatrix.sync.aligned.m8n8.x4.shared.b16 {%0,%1,%2,%3}, [%4];" \
                 : "=r"((r)[0]), "=r"((r)[1]), "=r"((r)[2]), "=r"((r)[3]) : "r"(addr))

__device__ __forceinline__ void mma_bf16(float* d, const uint32_t* a, const uint32_t* b) {
    asm volatile(
        "mma.sync.aligned.m16n8k16.row.col.f32.bf16.bf16.f32 "
        "{%0,%1,%2,%3}, {%4,%5,%6,%7}, {%8,%9}, {%0,%1,%2,%3};"
        : "+f"(d[0]), "+f"(d[1]), "+f"(d[2]), "+f"(d[3])
        : "r"(a[0]), "r"(a[1]), "r"(a[2]), "r"(a[3]), "r"(b[0]), "r"(b[1]));
}

// ======================= fp32 -> bf16 hi/lo split ==========================
__global__ void __launch_bounds__(256)
split_kernel(const float* __restrict__ src, __nv_bfloat16* __restrict__ hi,
             __nv_bfloat16* __restrict__ lo, int n4) {
    int i = blockIdx.x * blockDim.x + threadIdx.x;
    if (i >= n4) return;
    float4 v = ((const float4*)src)[i];
    __nv_bfloat16 h0 = __float2bfloat16(v.x), h1 = __float2bfloat16(v.y);
    __nv_bfloat16 h2 = __float2bfloat16(v.z), h3 = __float2bfloat16(v.w);
    __nv_bfloat16 l0 = __float2bfloat16(v.x - __bfloat162float(h0));
    __nv_bfloat16 l1 = __float2bfloat16(v.y - __bfloat162float(h1));
    __nv_bfloat16 l2 = __float2bfloat16(v.z - __bfloat162float(h2));
    __nv_bfloat16 l3 = __float2bfloat16(v.w - __bfloat162float(h3));
    ((__nv_bfloat162*)hi)[i * 2 + 0] = __nv_bfloat162{h0, h1};
    ((__nv_bfloat162*)hi)[i * 2 + 1] = __nv_bfloat162{h2, h3};
    ((__nv_bfloat162*)lo)[i * 2 + 0] = __nv_bfloat162{l0, l1};
    ((__nv_bfloat162*)lo)[i * 2 + 1] = __nv_bfloat162{l2, l3};
}

// ======================= bf16 mma.sync GEMM ================================
// C = (Ahi+Alo)(Bhi+Blo)^T + bias, drop lo*lo.  CTA tile 128x128, 16 warps,
// warp tile 32x32 (4x4 warp grid). KCH=64, 3-stage cp.async, XOR-swizzled
// 128B smem rows:  addr(r, c16) = r*128 + ((c16 ^ (r&7)) << 4)
#define KCH     64
#define NCHUNK  (GG / KCH)        // 64
#define MAT_B   (128 * 128)       // 16KB per 128x64-bf16 tile
#define A_HI_O  0
#define A_LO_O  (1 * MAT_B)
#define B_HI_O  (2 * MAT_B)
#define B_LO_O  (3 * MAT_B)
#define STAGE_B (4 * MAT_B)       // 64KB
#define NSTAGE  3
#define GEMM_SMEM (NSTAGE * STAGE_B)   // 192KB

__global__ void __launch_bounds__(512, 1)
gemm_mma_kernel(const __nv_bfloat16* __restrict__ Ahi, const __nv_bfloat16* __restrict__ Alo,
                const __nv_bfloat16* __restrict__ Bhi, const __nv_bfloat16* __restrict__ Blo,
                const float* __restrict__ bias, float* __restrict__ C) {
    extern __shared__ __align__(128) char smem[];
    const uint32_t sb = smem_u32(smem);
    const int tid  = threadIdx.x;
    const int wid  = tid >> 5, lane = tid & 31;
    const int wm   = wid & 3;          // 0..3 -> 32-row block
    const int wn   = wid >> 2;         // 0..3 -> 32-col block
    const int m0   = blockIdx.y * 128, n0 = blockIdx.x * 128;

    const __nv_bfloat16* pA0 = Ahi + (size_t)m0 * GG;
    const __nv_bfloat16* pA1 = Alo + (size_t)m0 * GG;
    const __nv_bfloat16* pB0 = Bhi + (size_t)n0 * GG;
    const __nv_bfloat16* pB1 = Blo + (size_t)n0 * GG;

    float acc[2][4][4];
#pragma unroll
    for (int i = 0; i < 2; i++)
#pragma unroll
        for (int j = 0; j < 4; j++)
#pragma unroll
            for (int r = 0; r < 4; r++) acc[i][j][r] = 0.0f;

    // ldmatrix per-lane constants
    // A: lanes 0-15 -> rows, lanes/16 -> k16-half select
    const uint32_t aRow  = (uint32_t)(wm * 32 + (lane & 15));
    const uint32_t aRowO = aRow * 128;
    const uint32_t aXor  = lane & 7;           // aRow & 7 (wm*32 multiple of 8)
    const uint32_t aHalf = (uint32_t)(lane >> 4);
    // B: lanes (0-7,8-15) -> rows n..n+7 @ kc 0/1 ; lanes (16-31) -> rows n+8..n+15
    const uint32_t bRow  = (uint32_t)(wn * 32 + (lane & 7) + ((lane >> 4) << 3));
    const uint32_t bRowO = bRow * 128;
    const uint32_t bXor  = lane & 7;           // bRow & 7
    const uint32_t bHalf = (uint32_t)((lane >> 3) & 1);

    // chunk loader: 4 matrices, 1024 x 16B each, 512 threads -> 8 CPA16/thread
    auto load_chunk = [&](int u, int s) {
        const uint32_t stb = sb + (uint32_t)s * STAGE_B;
        const size_t kof = (size_t)u * KCH;
#pragma unroll
        for (int j = 0; j < 2; ++j) {
            const int idx = tid + j * 512;
            const int row = idx >> 3, ch = idx & 7;
            const uint32_t so = (uint32_t)row * 128 + (uint32_t)((ch ^ (row & 7)) << 4);
            const size_t go = (size_t)row * GG + kof + (size_t)ch * 8;
            CPA16(stb + A_HI_O + so, pA0 + go);
            CPA16(stb + A_LO_O + so, pA1 + go);
            CPA16(stb + B_HI_O + so, pB0 + go);
            CPA16(stb + B_LO_O + so, pB1 + go);
        }
        CPA_COMMIT();
    };

    load_chunk(0, 0);
    load_chunk(1, 1);

    for (int t = 0; t < NCHUNK; ++t) {
        asm volatile("cp.async.wait_group 1;" ::: "memory");
        __syncthreads();
        if (t + 2 < NCHUNK) load_chunk(t + 2, (t + 2) % NSTAGE);

        const uint32_t stb = sb + (uint32_t)(t % NSTAGE) * STAGE_B;
        const uint32_t aHiB = stb + A_HI_O + aRowO;
        const uint32_t aLoB = stb + A_LO_O + aRowO;
        const uint32_t bHiB = stb + B_HI_O + bRowO;
        const uint32_t bLoB = stb + B_LO_O + bRowO;

#pragma unroll
        for (int ks = 0; ks < 4; ++ks) {
            uint32_t ah[2][4], al[2][4], bh[2][4], bl[2][4];
            const uint32_t ac16 = 2u * ks + aHalf;
            const uint32_t asw  = ((ac16 ^ aXor) << 4);
            const uint32_t bc16 = 2u * ks + bHalf;
            const uint32_t bsw  = ((bc16 ^ bXor) << 4);
#pragma unroll
            for (int mi = 0; mi < 2; ++mi) {
                LDSM4(ah[mi], aHiB + (uint32_t)mi * 2048 + asw);
                LDSM4(al[mi], aLoB + (uint32_t)mi * 2048 + asw);
            }
#pragma unroll
            for (int p = 0; p < 2; ++p) {
                LDSM4(bh[p], bHiB + (uint32_t)p * 2048 + bsw);
                LDSM4(bl[p], bLoB + (uint32_t)p * 2048 + bsw);
            }
#pragma unroll
            for (int mi = 0; mi < 2; ++mi)
#pragma unroll
                for (int p = 0; p < 2; ++p)
#pragma unroll
                    for (int q = 0; q < 2; ++q) {
                        const int ni = p * 2 + q;
                        mma_bf16(acc[mi][ni], ah[mi], &bh[p][q * 2]);
                        mma_bf16(acc[mi][ni], ah[mi], &bl[p][q * 2]);
                        mma_bf16(acc[mi][ni], al[mi], &bh[p][q * 2]);
                    }
        }
    }

    // epilogue
    const int rbase = m0 + wm * 32 + (lane >> 2);
    const int cbase = n0 + wn * 32 + (lane & 3) * 2;
#pragma unroll
    for (int mi = 0; mi < 2; ++mi) {
#pragma unroll
        for (int ni = 0; ni < 4; ++ni) {
            const int col = cbase + ni * 8;
            const float b0 = __ldg(&bias[col]), b1 = __ldg(&bias[col + 1]);
            const int r0 = rbase + mi * 16;
            float2 v0 = make_float2(acc[mi][ni][0] + b0, acc[mi][ni][1] + b1);
            float2 v1 = make_float2(acc[mi][ni][2] + b0, acc[mi][ni][3] + b1);
            *(float2*)&C[(size_t)r0 * NF + col]       = v0;
            *(float2*)&C[(size_t)(r0 + 8) * NF + col] = v1;
        }
    }
}

// ======================= downstream (unchanged, passing) ===================
__global__ void __launch_bounds__(256)
term_kernel(const float* __restrict__ in, int inStride,
            const float* __restrict__ termW, const float* __restrict__ termb,
            int off, int n, float* __restrict__ z) {
    const int t = blockIdx.y;
    __shared__ float Ws[144];
    __shared__ float bs[6];
    if (threadIdx.x < 144) Ws[threadIdx.x] = termW[(size_t)(off + t) * 144 + threadIdx.x];
    if (threadIdx.x < 6)   bs[threadIdx.x] = termb[(size_t)(off + t) * 6 + threadIdx.x];
    __syncthreads();
    const int b = blockIdx.x * blockDim.x + threadIdx.x;
    if (b >= BB) return;
    float xin[24];
    const float* ip = in + (size_t)b * inStride + t * 24;
#pragma unroll
    for (int i = 0; i < 24; i += 4) *(float4*)&xin[i] = *(const float4*)&ip[i];
    const int C = n * 6;
#pragma unroll
    for (int h = 0; h < 6; h++) {
        float s = bs[h];
#pragma unroll
        for (int i = 0; i < 24; i++) s = fmaf(xin[i], Ws[h * 24 + i], s);
        z[(size_t)b * C + t * 6 + h] = tanhf(s);
    }
}

__global__ void stats_kernel(const float* __restrict__ z, int C) {
    const int c = blockIdx.x * 32 + threadIdx.x;
    const int ty = threadIdx.y;
    double s = 0.0, sq = 0.0;
    if (c < C) {
        for (int b = ty; b < BB; b += 8) {
            float v = z[(size_t)b * C + c];
            s += v;
            sq += (double)v * v;
        }
    }
    __shared__ double sh_s[8][33];
    __shared__ double sh_q[8][33];
    sh_s[ty][threadIdx.x] = s;
    sh_q[ty][threadIdx.x] = sq;
    __syncthreads();
    if (ty == 0 && c < C) {
#pragma unroll
        for (int r = 1; r < 8; r++) { s += sh_s[r][threadIdx.x]; sq += sh_q[r][threadIdx.x]; }
        float mu = (float)(s / (double)BB);
        g_mean[c] = mu;
        g_var[c]  = (float)(sq / (double)BB - (double)mu * (double)mu);
    }
}

__global__ void __launch_bounds__(256)
bnaux_kernel(float* __restrict__ zh,
             const float* __restrict__ gamma, const float* __restrict__ beta,
             const float* __restrict__ a1W, const float* __restrict__ a1b,
             const float* __restrict__ a2W, const float* __restrict__ a2b,
             int off, int n, int colOff, float* __restrict__ out) {
    const int t = blockIdx.y;
    const int b = blockIdx.x * blockDim.x + threadIdx.x;
    if (b >= BB) return;
    const int C = n * 6;
    float a = a1b[off + t];
#pragma unroll
    for (int k = 0; k < 6; k++) {
        const int c = t * 6 + k;
        float v = zh[(size_t)b * C + c];
        float hv = (v - g_mean[c]) * rsqrtf(g_var[c] + EPSB) * gamma[(size_t)(off + t) * 6 + k]
                   + beta[(size_t)(off + t) * 6 + k];
        zh[(size_t)b * C + c] = hv;
        a = fmaf(hv, a1W[(size_t)(off + t) * 6 + k], a);
    }
    float a1 = tanhf(a);
    out[(size_t)b * OUTC + colOff + t] = fmaf(a1, a2W[off + t], a2b[off + t]);
}

__global__ void __launch_bounds__(256)
final1_kernel(const float* __restrict__ fW, const float* __restrict__ fb) {
    const int b = blockIdx.x * blockDim.x + threadIdx.x;
    if (b >= BB) return;
    float r[6];
#pragma unroll
    for (int i = 0; i < 6; i++) r[i] = g_h3[(size_t)b * 6 + i];
#pragma unroll
    for (int o = 0; o < 6; o++) {
        float s = fb[o];
#pragma unroll
        for (int i = 0; i < 6; i++) s = fmaf(r[i], fW[o * 6 + i], s);
        g_f[(size_t)b * 6 + o] = tanhf(s);
    }
}

__global__ void __launch_bounds__(256)
final2_kernel(const float* __restrict__ fg, const float* __restrict__ fbta,
              const float* __restrict__ fauxW, const float* __restrict__ fauxb,
              const float* __restrict__ foutW, const float* __restrict__ foutb,
              float* __restrict__ out) {
    const int b = blockIdx.x * blockDim.x + threadIdx.x;
    if (b >= BB) return;
    float a = fauxb[0];
#pragma unroll
    for (int h = 0; h < 6; h++) {
        float v = (g_f[(size_t)b * 6 + h] - g_mean[h]) * rsqrtf(g_var[h] + EPSB) * fg[h] + fbta[h];
        a = fmaf(v, fauxW[h], a);
    }
    float fa = tanhf(a);
    float p = fmaf(fa, foutW[0], foutb[0]);
    out[(size_t)b * OUTC + 85] = 1.0f / (1.0f + expf(-p));
}

// ---------------------------------------------------------------------------
extern "C" void kernel_launch(void* const* d_in, const int* in_sizes, int n_in,
                              void* d_out, int out_size) {
    (void)in_sizes; (void)n_in; (void)out_size;
    const float* x      = (const float*)d_in[0];
    const float* geneW  = (const float*)d_in[1];
    const float* geneb  = (const float*)d_in[2];
    const float* termW  = (const float*)d_in[3];
    const float* termb  = (const float*)d_in[4];
    const float* bng    = (const float*)d_in[5];
    const float* bnb    = (const float*)d_in[6];
    const float* a1W    = (const float*)d_in[7];
    const float* a1b    = (const float*)d_in[8];
    const float* a2W    = (const float*)d_in[9];
    const float* a2b    = (const float*)d_in[10];
    const float* finalW = (const float*)d_in[11];
    const float* finalb = (const float*)d_in[12];
    const float* fbng   = (const float*)d_in[13];
    const float* fbnb   = (const float*)d_in[14];
    const float* fauxW  = (const float*)d_in[15];
    const float* fauxb  = (const float*)d_in[16];
    const float* foutW  = (const float*)d_in[17];
    const float* foutb  = (const float*)d_in[18];
    float* out = (float*)d_out;

    float *hin, *h0, *h1, *h2, *h3, *f;
    __nv_bfloat16 *xhi, *xlo, *whi, *wlo;
    cudaGetSymbolAddress((void**)&hin, g_hin);
    cudaGetSymbolAddress((void**)&h0, g_h0);
    cudaGetSymbolAddress((void**)&h1, g_h1);
    cudaGetSymbolAddress((void**)&h2, g_h2);
    cudaGetSymbolAddress((void**)&h3, g_h3);
    cudaGetSymbolAddress((void**)&f, g_f);
    cudaGetSymbolAddress((void**)&xhi, g_xhi);
    cudaGetSymbolAddress((void**)&xlo, g_xlo);
    cudaGetSymbolAddress((void**)&whi, g_whi);
    cudaGetSymbolAddress((void**)&wlo, g_wlo);

    // 0) split fp32 -> bf16 hi/lo
    split_kernel<<<(BB * GG / 4 + 255) / 256, 256>>>(x, xhi, xlo, BB * GG / 4);
    split_kernel<<<(NF * GG / 4 + 255) / 256, 256>>>(geneW, whi, wlo, NF * GG / 4);

    // 1) gene layer GEMM via mma.sync bf16 (3-pass hi/lo)
    {
        cudaFuncSetAttribute(gemm_mma_kernel,
                             cudaFuncAttributeMaxDynamicSharedMemorySize, GEMM_SMEM);
        dim3 grid(NF / 128, BB / 128);
        gemm_mma_kernel<<<grid, 512, GEMM_SMEM>>>(xhi, xlo, whi, wlo, geneb, hin);
    }

    const int   lvl_n[4]        = {64, 16, 4, 1};
    const int   lvl_off[4]      = {0, 64, 80, 84};
    const int   lvl_inStride[4] = {NF, 384, 96, 24};
    const float* lvl_in[4]      = {hin, h0, h1, h2};
    float*      lvl_z[4]        = {h0, h1, h2, h3};

    for (int l = 0; l < 4; l++) {
        const int n = lvl_n[l], off = lvl_off[l];
        const int C = n * 6;
        dim3 gterm(BB / 256, n);
        term_kernel<<<gterm, 256>>>(lvl_in[l], lvl_inStride[l], termW, termb, off, n, lvl_z[l]);
        dim3 gstat((C + 31) / 32);
        stats_kernel<<<gstat, dim3(32, 8)>>>(lvl_z[l], C);
        bnaux_kernel<<<gterm, 256>>>(lvl_z[l], bng, bnb, a1W, a1b, a2W, a2b,
                                     off, n, off, out);
    }

    final1_kernel<<<BB / 256, 256>>>(finalW, finalb);
    stats_kernel<<<1, dim3(32, 8)>>>(f, 6);
    final2_kernel<<<BB / 256, 256>>>(fbng, fbnb, fauxW, fauxb, foutW, foutb, out);
}

// round 6
// speedup vs baseline: 3.2617x; 1.3833x over previous
#include <cuda_runtime.h>
#include <cuda_bf16.h>
#include <math.h>
#include <stdint.h>

// Problem constants
#define BB   4096
#define GG   4096
#define NF2  384               // fused gene+term0 output width (64 terms x 6)
#define OUTC 86
#define EPSB 1e-5f

// ---------------- scratch (device globals) ---------------------------------
__device__ __align__(16) float g_h0[BB * 384];
__device__ __align__(16) float g_h1[BB * 96];
__device__ __align__(16) float g_h2[BB * 24];
__device__ __align__(16) float g_h3[BB * 6];
__device__ __align__(16) float g_f [BB * 6];
__device__ float g_mean[512];
__device__ float g_var [512];
__device__ __align__(16) __nv_bfloat16 g_xhi[BB * GG];
__device__ __align__(16) __nv_bfloat16 g_xlo[BB * GG];
__device__ __align__(16) __nv_bfloat16 g_weffhi[NF2 * GG];
__device__ __align__(16) __nv_bfloat16 g_wefflo[NF2 * GG];
__device__ float g_beff[NF2];

// ======================= helpers ===========================================
__device__ __forceinline__ uint32_t smem_u32(const void* p) {
    uint32_t a;
    asm("{ .reg .u64 t; cvta.to.shared.u64 t, %1; cvt.u32.u64 %0, t; }" : "=r"(a) : "l"(p));
    return a;
}
#define CPA16(dst, src) \
    asm volatile("cp.async.cg.shared.global [%0], [%1], 16;" :: "r"(dst), "l"(src))
#define CPA_COMMIT() asm volatile("cp.async.commit_group;" ::: "memory")

#define LDSM4(r, addr) \
    asm volatile("ldmatrix.sync.aligned.m8n8.x4.shared.b16 {%0,%1,%2,%3}, [%4];" \
                 : "=r"((r)[0]), "=r"((r)[1]), "=r"((r)[2]), "=r"((r)[3]) : "r"(addr))

__device__ __forceinline__ void mma_bf16(float* d, const uint32_t* a, const uint32_t* b) {
    asm volatile(
        "mma.sync.aligned.m16n8k16.row.col.f32.bf16.bf16.f32 "
        "{%0,%1,%2,%3}, {%4,%5,%6,%7}, {%8,%9}, {%0,%1,%2,%3};"
        : "+f"(d[0]), "+f"(d[1]), "+f"(d[2]), "+f"(d[3])
        : "r"(a[0]), "r"(a[1]), "r"(a[2]), "r"(a[3]), "r"(b[0]), "r"(b[1]));
}

// ======================= fp32 -> bf16 hi/lo split ==========================
__global__ void __launch_bounds__(256)
split_kernel(const float* __restrict__ src, __nv_bfloat16* __restrict__ hi,
             __nv_bfloat16* __restrict__ lo, int n4) {
    int i = blockIdx.x * blockDim.x + threadIdx.x;
    if (i >= n4) return;
    float4 v = ((const float4*)src)[i];
    __nv_bfloat16 h0 = __float2bfloat16(v.x), h1 = __float2bfloat16(v.y);
    __nv_bfloat16 h2 = __float2bfloat16(v.z), h3 = __float2bfloat16(v.w);
    __nv_bfloat16 l0 = __float2bfloat16(v.x - __bfloat162float(h0));
    __nv_bfloat16 l1 = __float2bfloat16(v.y - __bfloat162float(h1));
    __nv_bfloat16 l2 = __float2bfloat16(v.z - __bfloat162float(h2));
    __nv_bfloat16 l3 = __float2bfloat16(v.w - __bfloat162float(h3));
    ((__nv_bfloat162*)hi)[i * 2 + 0] = __nv_bfloat162{h0, h1};
    ((__nv_bfloat162*)hi)[i * 2 + 1] = __nv_bfloat162{h2, h3};
    ((__nv_bfloat162*)lo)[i * 2 + 0] = __nv_bfloat162{l0, l1};
    ((__nv_bfloat162*)lo)[i * 2 + 1] = __nv_bfloat162{l2, l3};
}

// ======================= W_eff precompute ==================================
// W_eff[t*6+h, g] = sum_k term_W[t,h,k] * gene_W[t,k,g]   (fp32, split hi/lo)
// b_eff[t*6+h]    = term_b[t,h] + sum_k term_W[t,h,k] * gene_b[t,k]
__global__ void __launch_bounds__(256)
weff_kernel(const float* __restrict__ geneW, const float* __restrict__ geneb,
            const float* __restrict__ termW, const float* __restrict__ termb,
            __nv_bfloat16* __restrict__ whi, __nv_bfloat16* __restrict__ wlo,
            float* __restrict__ beff) {
    const int t = blockIdx.y;
    __shared__ float tw[144];
    if (threadIdx.x < 144) tw[threadIdx.x] = termW[(size_t)t * 144 + threadIdx.x];
    __syncthreads();
    const int g = blockIdx.x * 256 + threadIdx.x;
    float gw[24];
#pragma unroll
    for (int k = 0; k < 24; k++) gw[k] = geneW[((size_t)t * 24 + k) * GG + g];
#pragma unroll
    for (int h = 0; h < 6; h++) {
        float s = 0.0f;
#pragma unroll
        for (int k = 0; k < 24; k++) s = fmaf(tw[h * 24 + k], gw[k], s);
        __nv_bfloat16 hi = __float2bfloat16(s);
        float lo = s - __bfloat162float(hi);
        whi[((size_t)(t * 6 + h)) * GG + g] = hi;
        wlo[((size_t)(t * 6 + h)) * GG + g] = __float2bfloat16(lo);
    }
    if (blockIdx.x == 0 && threadIdx.x < 6) {
        const int h = threadIdx.x;
        float s = termb[t * 6 + h];
#pragma unroll
        for (int k = 0; k < 24; k++) s = fmaf(tw[h * 24 + k], geneb[t * 24 + k], s);
        beff[t * 6 + h] = s;
    }
}

// ======================= fused bf16 GEMM + tanh ============================
// z[b,n] = tanh( (xhi+xlo)[b,:] . (Whi+Wlo)[n,:] + beff[n] ), drop lo*lo.
// CTA tile 64(M)x128(N), 8 warps (warp tile 32x32, grid 2x4), KCH=64,
// 2-stage cp.async, XOR-swizzled 128B rows. 2 CTAs/SM.
#define KCH     64
#define NCHUNK  (GG / KCH)        // 64
#define A_HI_O  0
#define A_LO_O  8192
#define B_HI_O  16384
#define B_LO_O  32768
#define STAGE_B 49152             // 48KB
#define GEMM_SMEM (2 * STAGE_B)   // 96KB

__global__ void __launch_bounds__(256, 2)
gemm_fused_kernel(const __nv_bfloat16* __restrict__ Ahi, const __nv_bfloat16* __restrict__ Alo,
                  const __nv_bfloat16* __restrict__ Bhi, const __nv_bfloat16* __restrict__ Blo,
                  const float* __restrict__ beff, float* __restrict__ Z) {
    extern __shared__ __align__(128) char smem[];
    const uint32_t sb = smem_u32(smem);
    const int tid  = threadIdx.x;
    const int wid  = tid >> 5, lane = tid & 31;
    const int wm   = wid & 1;          // 0..1 -> 32-row block
    const int wn   = wid >> 1;         // 0..3 -> 32-col block
    const int m0   = blockIdx.y * 64, n0 = blockIdx.x * 128;

    const __nv_bfloat16* pA0 = Ahi + (size_t)m0 * GG;
    const __nv_bfloat16* pA1 = Alo + (size_t)m0 * GG;
    const __nv_bfloat16* pB0 = Bhi + (size_t)n0 * GG;
    const __nv_bfloat16* pB1 = Blo + (size_t)n0 * GG;

    float acc[2][4][4];
#pragma unroll
    for (int i = 0; i < 2; i++)
#pragma unroll
        for (int j = 0; j < 4; j++)
#pragma unroll
            for (int r = 0; r < 4; r++) acc[i][j][r] = 0.0f;

    const uint32_t aRow  = (uint32_t)(wm * 32 + (lane & 15));
    const uint32_t aRowO = aRow * 128;
    const uint32_t aXor  = lane & 7;
    const uint32_t aHalf = (uint32_t)(lane >> 4);
    const uint32_t bRow  = (uint32_t)(wn * 32 + (lane & 7) + ((lane >> 4) << 3));
    const uint32_t bRowO = bRow * 128;
    const uint32_t bXor  = lane & 7;
    const uint32_t bHalf = (uint32_t)((lane >> 3) & 1);

    auto load_chunk = [&](int u, int s) {
        const uint32_t stb = sb + (uint32_t)s * STAGE_B;
        const size_t kof = (size_t)u * KCH;
        // A: 64 rows x 8 chunks = 512 per matrix
#pragma unroll
        for (int j = 0; j < 2; ++j) {
            const int idx = tid + j * 256;
            const int row = idx >> 3, ch = idx & 7;
            const uint32_t so = (uint32_t)row * 128 + (uint32_t)((ch ^ (row & 7)) << 4);
            const size_t go = (size_t)row * GG + kof + (size_t)ch * 8;
            CPA16(stb + A_HI_O + so, pA0 + go);
            CPA16(stb + A_LO_O + so, pA1 + go);
        }
        // B: 128 rows x 8 chunks = 1024 per matrix
#pragma unroll
        for (int j = 0; j < 4; ++j) {
            const int idx = tid + j * 256;
            const int row = idx >> 3, ch = idx & 7;
            const uint32_t so = (uint32_t)row * 128 + (uint32_t)((ch ^ (row & 7)) << 4);
            const size_t go = (size_t)row * GG + kof + (size_t)ch * 8;
            CPA16(stb + B_HI_O + so, pB0 + go);
            CPA16(stb + B_LO_O + so, pB1 + go);
        }
        CPA_COMMIT();
    };

    load_chunk(0, 0);

    for (int t = 0; t < NCHUNK; ++t) {
        if (t + 1 < NCHUNK) {
            load_chunk(t + 1, (t + 1) & 1);
            asm volatile("cp.async.wait_group 1;" ::: "memory");
        } else {
            asm volatile("cp.async.wait_group 0;" ::: "memory");
        }
        __syncthreads();

        const uint32_t stb = sb + (uint32_t)(t & 1) * STAGE_B;
        const uint32_t aHiB = stb + A_HI_O + aRowO;
        const uint32_t aLoB = stb + A_LO_O + aRowO;
        const uint32_t bHiB = stb + B_HI_O + bRowO;
        const uint32_t bLoB = stb + B_LO_O + bRowO;

#pragma unroll
        for (int ks = 0; ks < 4; ++ks) {
            uint32_t ah[2][4], al[2][4], bh[2][4], bl[2][4];
            const uint32_t asw = (((2u * ks + aHalf) ^ aXor) << 4);
            const uint32_t bsw = (((2u * ks + bHalf) ^ bXor) << 4);
#pragma unroll
            for (int mi = 0; mi < 2; ++mi) {
                LDSM4(ah[mi], aHiB + (uint32_t)mi * 2048 + asw);
                LDSM4(al[mi], aLoB + (uint32_t)mi * 2048 + asw);
            }
#pragma unroll
            for (int p = 0; p < 2; ++p) {
                LDSM4(bh[p], bHiB + (uint32_t)p * 2048 + bsw);
                LDSM4(bl[p], bLoB + (uint32_t)p * 2048 + bsw);
            }
#pragma unroll
            for (int mi = 0; mi < 2; ++mi)
#pragma unroll
                for (int p = 0; p < 2; ++p)
#pragma unroll
                    for (int q = 0; q < 2; ++q) {
                        const int ni = p * 2 + q;
                        mma_bf16(acc[mi][ni], ah[mi], &bh[p][q * 2]);
                        mma_bf16(acc[mi][ni], ah[mi], &bl[p][q * 2]);
                        mma_bf16(acc[mi][ni], al[mi], &bh[p][q * 2]);
                    }
        }
        __syncthreads();
    }

    // epilogue: tanh(acc + beff)
    const int rbase = m0 + wm * 32 + (lane >> 2);
    const int cbase = n0 + wn * 32 + (lane & 3) * 2;
#pragma unroll
    for (int mi = 0; mi < 2; ++mi) {
#pragma unroll
        for (int ni = 0; ni < 4; ++ni) {
            const int col = cbase + ni * 8;
            const float b0 = __ldg(&beff[col]), b1 = __ldg(&beff[col + 1]);
            const int r0 = rbase + mi * 16;
            float2 v0 = make_float2(tanhf(acc[mi][ni][0] + b0), tanhf(acc[mi][ni][1] + b1));
            float2 v1 = make_float2(tanhf(acc[mi][ni][2] + b0), tanhf(acc[mi][ni][3] + b1));
            *(float2*)&Z[(size_t)r0 * NF2 + col]       = v0;
            *(float2*)&Z[(size_t)(r0 + 8) * NF2 + col] = v1;
        }
    }
}

// ======================= downstream ========================================
__global__ void __launch_bounds__(256)
term_kernel(const float* __restrict__ in, int inStride,
            const float* __restrict__ termW, const float* __restrict__ termb,
            int off, int n, float* __restrict__ z) {
    const int t = blockIdx.y;
    __shared__ float Ws[144];
    __shared__ float bs[6];
    if (threadIdx.x < 144) Ws[threadIdx.x] = termW[(size_t)(off + t) * 144 + threadIdx.x];
    if (threadIdx.x < 6)   bs[threadIdx.x] = termb[(size_t)(off + t) * 6 + threadIdx.x];
    __syncthreads();
    const int b = blockIdx.x * blockDim.x + threadIdx.x;
    if (b >= BB) return;
    float xin[24];
    const float* ip = in + (size_t)b * inStride + t * 24;
#pragma unroll
    for (int i = 0; i < 24; i += 4) *(float4*)&xin[i] = *(const float4*)&ip[i];
    const int C = n * 6;
#pragma unroll
    for (int h = 0; h < 6; h++) {
        float s = bs[h];
#pragma unroll
        for (int i = 0; i < 24; i++) s = fmaf(xin[i], Ws[h * 24 + i], s);
        z[(size_t)b * C + t * 6 + h] = tanhf(s);
    }
}

__global__ void stats_kernel(const float* __restrict__ z, int C) {
    const int c = blockIdx.x * 32 + threadIdx.x;
    const int ty = threadIdx.y;
    double s = 0.0, sq = 0.0;
    if (c < C) {
        for (int b = ty; b < BB; b += 8) {
            float v = z[(size_t)b * C + c];
            s += v;
            sq += (double)v * v;
        }
    }
    __shared__ double sh_s[8][33];
    __shared__ double sh_q[8][33];
    sh_s[ty][threadIdx.x] = s;
    sh_q[ty][threadIdx.x] = sq;
    __syncthreads();
    if (ty == 0 && c < C) {
#pragma unroll
        for (int r = 1; r < 8; r++) { s += sh_s[r][threadIdx.x]; sq += sh_q[r][threadIdx.x]; }
        float mu = (float)(s / (double)BB);
        g_mean[c] = mu;
        g_var[c]  = (float)(sq / (double)BB - (double)mu * (double)mu);
    }
}

__global__ void __launch_bounds__(256)
bnaux_kernel(float* __restrict__ zh,
             const float* __restrict__ gamma, const float* __restrict__ beta,
             const float* __restrict__ a1W, const float* __restrict__ a1b,
             const float* __restrict__ a2W, const float* __restrict__ a2b,
             int off, int n, int colOff, float* __restrict__ out) {
    const int t = blockIdx.y;
    const int b = blockIdx.x * blockDim.x + threadIdx.x;
    if (b >= BB) return;
    const int C = n * 6;
    float a = a1b[off + t];
#pragma unroll
    for (int k = 0; k < 6; k++) {
        const int c = t * 6 + k;
        float v = zh[(size_t)b * C + c];
        float hv = (v - g_mean[c]) * rsqrtf(g_var[c] + EPSB) * gamma[(size_t)(off + t) * 6 + k]
                   + beta[(size_t)(off + t) * 6 + k];
        zh[(size_t)b * C + c] = hv;
        a = fmaf(hv, a1W[(size_t)(off + t) * 6 + k], a);
    }
    float a1 = tanhf(a);
    out[(size_t)b * OUTC + colOff + t] = fmaf(a1, a2W[off + t], a2b[off + t]);
}

__global__ void __launch_bounds__(256)
final1_kernel(const float* __restrict__ fW, const float* __restrict__ fb) {
    const int b = blockIdx.x * blockDim.x + threadIdx.x;
    if (b >= BB) return;
    float r[6];
#pragma unroll
    for (int i = 0; i < 6; i++) r[i] = g_h3[(size_t)b * 6 + i];
#pragma unroll
    for (int o = 0; o < 6; o++) {
        float s = fb[o];
#pragma unroll
        for (int i = 0; i < 6; i++) s = fmaf(r[i], fW[o * 6 + i], s);
        g_f[(size_t)b * 6 + o] = tanhf(s);
    }
}

__global__ void __launch_bounds__(256)
final2_kernel(const float* __restrict__ fg, const float* __restrict__ fbta,
              const float* __restrict__ fauxW, const float* __restrict__ fauxb,
              const float* __restrict__ foutW, const float* __restrict__ foutb,
              float* __restrict__ out) {
    const int b = blockIdx.x * blockDim.x + threadIdx.x;
    if (b >= BB) return;
    float a = fauxb[0];
#pragma unroll
    for (int h = 0; h < 6; h++) {
        float v = (g_f[(size_t)b * 6 + h] - g_mean[h]) * rsqrtf(g_var[h] + EPSB) * fg[h] + fbta[h];
        a = fmaf(v, fauxW[h], a);
    }
    float fa = tanhf(a);
    float p = fmaf(fa, foutW[0], foutb[0]);
    out[(size_t)b * OUTC + 85] = 1.0f / (1.0f + expf(-p));
}

// ---------------------------------------------------------------------------
extern "C" void kernel_launch(void* const* d_in, const int* in_sizes, int n_in,
                              void* d_out, int out_size) {
    (void)in_sizes; (void)n_in; (void)out_size;
    const float* x      = (const float*)d_in[0];
    const float* geneW  = (const float*)d_in[1];
    const float* geneb  = (const float*)d_in[2];
    const float* termW  = (const float*)d_in[3];
    const float* termb  = (const float*)d_in[4];
    const float* bng    = (const float*)d_in[5];
    const float* bnb    = (const float*)d_in[6];
    const float* a1W    = (const float*)d_in[7];
    const float* a1b    = (const float*)d_in[8];
    const float* a2W    = (const float*)d_in[9];
    const float* a2b    = (const float*)d_in[10];
    const float* finalW = (const float*)d_in[11];
    const float* finalb = (const float*)d_in[12];
    const float* fbng   = (const float*)d_in[13];
    const float* fbnb   = (const float*)d_in[14];
    const float* fauxW  = (const float*)d_in[15];
    const float* fauxb  = (const float*)d_in[16];
    const float* foutW  = (const float*)d_in[17];
    const float* foutb  = (const float*)d_in[18];
    float* out = (float*)d_out;

    float *h0, *h1, *h2, *h3, *f, *beff;
    __nv_bfloat16 *xhi, *xlo, *whi, *wlo;
    cudaGetSymbolAddress((void**)&h0, g_h0);
    cudaGetSymbolAddress((void**)&h1, g_h1);
    cudaGetSymbolAddress((void**)&h2, g_h2);
    cudaGetSymbolAddress((void**)&h3, g_h3);
    cudaGetSymbolAddress((void**)&f, g_f);
    cudaGetSymbolAddress((void**)&xhi, g_xhi);
    cudaGetSymbolAddress((void**)&xlo, g_xlo);
    cudaGetSymbolAddress((void**)&whi, g_weffhi);
    cudaGetSymbolAddress((void**)&wlo, g_wefflo);
    cudaGetSymbolAddress((void**)&beff, g_beff);

    // 0) x split + W_eff precompute (independent)
    split_kernel<<<(BB * GG / 4 + 255) / 256, 256>>>(x, xhi, xlo, BB * GG / 4);
    {
        dim3 g(GG / 256, 64);
        weff_kernel<<<g, 256>>>(geneW, geneb, termW, termb, whi, wlo, beff);
    }

    // 1) fused gene+term0 GEMM -> z level0 (tanh applied)
    {
        cudaFuncSetAttribute(gemm_fused_kernel,
                             cudaFuncAttributeMaxDynamicSharedMemorySize, GEMM_SMEM);
        dim3 grid(NF2 / 128, BB / 64);
        gemm_fused_kernel<<<grid, 256, GEMM_SMEM>>>(xhi, xlo, whi, wlo, beff, h0);
    }

    // 2) level0 BN + aux (z already computed)
    {
        dim3 gterm(BB / 256, 64);
        stats_kernel<<<(384 + 31) / 32, dim3(32, 8)>>>(h0, 384);
        bnaux_kernel<<<gterm, 256>>>(h0, bng, bnb, a1W, a1b, a2W, a2b, 0, 64, 0, out);
    }

    // 3) levels 1-3
    const int   lvl_n[3]        = {16, 4, 1};
    const int   lvl_off[3]      = {64, 80, 84};
    const int   lvl_inStride[3] = {384, 96, 24};
    const float* lvl_in[3]      = {h0, h1, h2};
    float*      lvl_z[3]        = {h1, h2, h3};

    for (int l = 0; l < 3; l++) {
        const int n = lvl_n[l], off = lvl_off[l];
        const int C = n * 6;
        dim3 gterm(BB / 256, n);
        term_kernel<<<gterm, 256>>>(lvl_in[l], lvl_inStride[l], termW, termb, off, n, lvl_z[l]);
        stats_kernel<<<(C + 31) / 32, dim3(32, 8)>>>(lvl_z[l], C);
        bnaux_kernel<<<gterm, 256>>>(lvl_z[l], bng, bnb, a1W, a1b, a2W, a2b,
                                     off, n, off, out);
    }

    // 4) final head
    final1_kernel<<<BB / 256, 256>>>(finalW, finalb);
    stats_kernel<<<1, dim3(32, 8)>>>(f, 6);
    final2_kernel<<<BB / 256, 256>>>(fbng, fbnb, fauxW, fauxb, foutW, foutb, out);
}

// round 9
// speedup vs baseline: 9.1505x; 2.8055x over previous
#include <cuda_runtime.h>
#include <cuda_bf16.h>
#include <math.h>
#include <stdint.h>

// Problem constants
#define BB   4096
#define GG   4096
#define NF2  384               // fused gene+term0 output width (64 terms x 6)
#define OUTC 86
#define EPSB 1e-5f
#define NSLI 32                // stats phase-1 batch slices

// ---------------- scratch (device globals) ---------------------------------
__device__ __align__(16) float g_h0[BB * 384];
__device__ __align__(16) float g_h1[BB * 96];
__device__ __align__(16) float g_h2[BB * 24];
__device__ __align__(16) float g_h3[BB * 6];
__device__ __align__(16) float g_f [BB * 6];
__device__ float g_mean[512];
__device__ float g_var [512];
__device__ float g_psum[NSLI * 512];
__device__ float g_psq [NSLI * 512];
__device__ __align__(16) __nv_bfloat16 g_xhi[BB * GG];
__device__ __align__(16) __nv_bfloat16 g_xlo[BB * GG];
__device__ __align__(16) __nv_bfloat16 g_weffhi[NF2 * GG];
__device__ __align__(16) __nv_bfloat16 g_wefflo[NF2 * GG];
__device__ float g_beff[NF2];

// ======================= helpers ===========================================
__device__ __forceinline__ uint32_t smem_u32(const void* p) {
    uint32_t a;
    asm("{ .reg .u64 t; cvta.to.shared.u64 t, %1; cvt.u32.u64 %0, t; }" : "=r"(a) : "l"(p));
    return a;
}
#define CPA16(dst, src) \
    asm volatile("cp.async.cg.shared.global [%0], [%1], 16;" :: "r"(dst), "l"(src))
#define CPA_COMMIT() asm volatile("cp.async.commit_group;" ::: "memory")

#define LDSM4(r, addr) \
    asm volatile("ldmatrix.sync.aligned.m8n8.x4.shared.b16 {%0,%1,%2,%3}, [%4];" \
                 : "=r"((r)[0]), "=r"((r)[1]), "=r"((r)[2]), "=r"((r)[3]) : "r"(addr))

__device__ __forceinline__ void mma_bf16(float* d, const uint32_t* a, const uint32_t* b) {
    asm volatile(
        "mma.sync.aligned.m16n8k16.row.col.f32.bf16.bf16.f32 "
        "{%0,%1,%2,%3}, {%4,%5,%6,%7}, {%8,%9}, {%0,%1,%2,%3};"
        : "+f"(d[0]), "+f"(d[1]), "+f"(d[2]), "+f"(d[3])
        : "r"(a[0]), "r"(a[1]), "r"(a[2]), "r"(a[3]), "r"(b[0]), "r"(b[1]));
}

// ======================= fp32 -> bf16 hi/lo split ==========================
__global__ void __launch_bounds__(256)
split_kernel(const float* __restrict__ src, __nv_bfloat16* __restrict__ hi,
             __nv_bfloat16* __restrict__ lo, int n4) {
    int i = blockIdx.x * blockDim.x + threadIdx.x;
    if (i >= n4) return;
    float4 v = ((const float4*)src)[i];
    __nv_bfloat16 h0 = __float2bfloat16(v.x), h1 = __float2bfloat16(v.y);
    __nv_bfloat16 h2 = __float2bfloat16(v.z), h3 = __float2bfloat16(v.w);
    __nv_bfloat16 l0 = __float2bfloat16(v.x - __bfloat162float(h0));
    __nv_bfloat16 l1 = __float2bfloat16(v.y - __bfloat162float(h1));
    __nv_bfloat16 l2 = __float2bfloat16(v.z - __bfloat162float(h2));
    __nv_bfloat16 l3 = __float2bfloat16(v.w - __bfloat162float(h3));
    ((__nv_bfloat162*)hi)[i * 2 + 0] = __nv_bfloat162{h0, h1};
    ((__nv_bfloat162*)hi)[i * 2 + 1] = __nv_bfloat162{h2, h3};
    ((__nv_bfloat162*)lo)[i * 2 + 0] = __nv_bfloat162{l0, l1};
    ((__nv_bfloat162*)lo)[i * 2 + 1] = __nv_bfloat162{l2, l3};
}

// ======================= W_eff precompute ==================================
__global__ void __launch_bounds__(256)
weff_kernel(const float* __restrict__ geneW, const float* __restrict__ geneb,
            const float* __restrict__ termW, const float* __restrict__ termb,
            __nv_bfloat16* __restrict__ whi, __nv_bfloat16* __restrict__ wlo,
            float* __restrict__ beff) {
    const int t = blockIdx.y;
    __shared__ float tw[144];
    if (threadIdx.x < 144) tw[threadIdx.x] = termW[(size_t)t * 144 + threadIdx.x];
    __syncthreads();
    const int g = blockIdx.x * 256 + threadIdx.x;
    float gw[24];
#pragma unroll
    for (int k = 0; k < 24; k++) gw[k] = geneW[((size_t)t * 24 + k) * GG + g];
#pragma unroll
    for (int h = 0; h < 6; h++) {
        float s = 0.0f;
#pragma unroll
        for (int k = 0; k < 24; k++) s = fmaf(tw[h * 24 + k], gw[k], s);
        __nv_bfloat16 hi = __float2bfloat16(s);
        float lo = s - __bfloat162float(hi);
        whi[((size_t)(t * 6 + h)) * GG + g] = hi;
        wlo[((size_t)(t * 6 + h)) * GG + g] = __float2bfloat16(lo);
    }
    if (blockIdx.x == 0 && threadIdx.x < 6) {
        const int h = threadIdx.x;
        float s = termb[t * 6 + h];
#pragma unroll
        for (int k = 0; k < 24; k++) s = fmaf(tw[h * 24 + k], geneb[t * 24 + k], s);
        beff[t * 6 + h] = s;
    }
}

// ======================= fused bf16 GEMM + tanh ============================
// CTA tile 64(M)x64(N), 4 warps (warp tile 32x32), KCH=64, 2-stage cp.async,
// XOR-swizzled 128B rows, 3 CTAs/SM. grid = (6, 64) = 384 CTAs.
#define KCH     64
#define NCHUNK  (GG / KCH)        // 64
#define A_HI_O  0
#define A_LO_O  8192
#define B_HI_O  16384
#define B_LO_O  24576
#define STAGE_B 32768             // 32KB
#define GEMM_SMEM (2 * STAGE_B)   // 64KB

__global__ void __launch_bounds__(128, 3)
gemm_fused_kernel(const __nv_bfloat16* __restrict__ Ahi, const __nv_bfloat16* __restrict__ Alo,
                  const __nv_bfloat16* __restrict__ Bhi, const __nv_bfloat16* __restrict__ Blo,
                  const float* __restrict__ beff, float* __restrict__ Z) {
    extern __shared__ __align__(128) char smem[];
    const uint32_t sb = smem_u32(smem);
    const int tid  = threadIdx.x;
    const int wid  = tid >> 5, lane = tid & 31;
    const int wm   = wid & 1;          // 0..1 -> 32-row block
    const int wn   = wid >> 1;         // 0..1 -> 32-col block
    const int m0   = blockIdx.y * 64, n0 = blockIdx.x * 64;

    const __nv_bfloat16* pA0 = Ahi + (size_t)m0 * GG;
    const __nv_bfloat16* pA1 = Alo + (size_t)m0 * GG;
    const __nv_bfloat16* pB0 = Bhi + (size_t)n0 * GG;
    const __nv_bfloat16* pB1 = Blo + (size_t)n0 * GG;

    float acc[2][4][4];
#pragma unroll
    for (int i = 0; i < 2; i++)
#pragma unroll
        for (int j = 0; j < 4; j++)
#pragma unroll
            for (int r = 0; r < 4; r++) acc[i][j][r] = 0.0f;

    const uint32_t aRowO = (uint32_t)(wm * 32 + (lane & 15)) * 128;
    const uint32_t aXor  = lane & 7;
    const uint32_t aHalf = (uint32_t)(lane >> 4);
    const uint32_t bRowO = (uint32_t)(wn * 32 + (lane & 7) + ((lane >> 4) << 3)) * 128;
    const uint32_t bXor  = lane & 7;
    const uint32_t bHalf = (uint32_t)((lane >> 3) & 1);

    // 64 rows x 8 chunks = 512 16B-items per matrix; 128 threads -> 4 iters
    auto load_chunk = [&](int u, int s) {
        const uint32_t stb = sb + (uint32_t)s * STAGE_B;
        const size_t kof = (size_t)u * KCH;
#pragma unroll
        for (int j = 0; j < 4; ++j) {
            const int idx = tid + j * 128;
            const int row = idx >> 3, ch = idx & 7;
            const uint32_t so = (uint32_t)row * 128 + (uint32_t)((ch ^ (row & 7)) << 4);
            const size_t go = (size_t)row * GG + kof + (size_t)ch * 8;
            CPA16(stb + A_HI_O + so, pA0 + go);
            CPA16(stb + A_LO_O + so, pA1 + go);
            CPA16(stb + B_HI_O + so, pB0 + go);
            CPA16(stb + B_LO_O + so, pB1 + go);
        }
        CPA_COMMIT();
    };

    load_chunk(0, 0);

    for (int t = 0; t < NCHUNK; ++t) {
        if (t + 1 < NCHUNK) {
            load_chunk(t + 1, (t + 1) & 1);
            asm volatile("cp.async.wait_group 1;" ::: "memory");
        } else {
            asm volatile("cp.async.wait_group 0;" ::: "memory");
        }
        __syncthreads();

        const uint32_t stb = sb + (uint32_t)(t & 1) * STAGE_B;
        const uint32_t aHiB = stb + A_HI_O + aRowO;
        const uint32_t aLoB = stb + A_LO_O + aRowO;
        const uint32_t bHiB = stb + B_HI_O + bRowO;
        const uint32_t bLoB = stb + B_LO_O + bRowO;

#pragma unroll
        for (int ks = 0; ks < 4; ++ks) {
            uint32_t ah[2][4], al[2][4], bh[2][4], bl[2][4];
            const uint32_t asw = (((2u * ks + aHalf) ^ aXor) << 4);
            const uint32_t bsw = (((2u * ks + bHalf) ^ bXor) << 4);
#pragma unroll
            for (int mi = 0; mi < 2; ++mi) {
                LDSM4(ah[mi], aHiB + (uint32_t)mi * 2048 + asw);
                LDSM4(al[mi], aLoB + (uint32_t)mi * 2048 + asw);
            }
#pragma unroll
            for (int p = 0; p < 2; ++p) {
                LDSM4(bh[p], bHiB + (uint32_t)p * 2048 + bsw);
                LDSM4(bl[p], bLoB + (uint32_t)p * 2048 + bsw);
            }
#pragma unroll
            for (int mi = 0; mi < 2; ++mi)
#pragma unroll
                for (int p = 0; p < 2; ++p)
#pragma unroll
                    for (int q = 0; q < 2; ++q) {
                        const int ni = p * 2 + q;
                        mma_bf16(acc[mi][ni], ah[mi], &bh[p][q * 2]);
                        mma_bf16(acc[mi][ni], ah[mi], &bl[p][q * 2]);
                        mma_bf16(acc[mi][ni], al[mi], &bh[p][q * 2]);
                    }
        }
        __syncthreads();
    }

    // epilogue: tanh(acc + beff)
    const int rbase = m0 + wm * 32 + (lane >> 2);
    const int cbase = n0 + wn * 32 + (lane & 3) * 2;
#pragma unroll
    for (int mi = 0; mi < 2; ++mi) {
#pragma unroll
        for (int ni = 0; ni < 4; ++ni) {
            const int col = cbase + ni * 8;
            const float b0 = __ldg(&beff[col]), b1 = __ldg(&beff[col + 1]);
            const int r0 = rbase + mi * 16;
            float2 v0 = make_float2(tanhf(acc[mi][ni][0] + b0), tanhf(acc[mi][ni][1] + b1));
            float2 v1 = make_float2(tanhf(acc[mi][ni][2] + b0), tanhf(acc[mi][ni][3] + b1));
            *(float2*)&Z[(size_t)r0 * NF2 + col]       = v0;
            *(float2*)&Z[(size_t)(r0 + 8) * NF2 + col] = v1;
        }
    }
}

// ======================= two-phase BN stats ================================
// phase1: slice s covers rows [s*128, (s+1)*128); thread -> channel (coalesced)
__global__ void __launch_bounds__(256)
stats1_kernel(const float* __restrict__ z, int C) {
    const int c = blockIdx.x * 256 + threadIdx.x;
    const int s = blockIdx.y;
    if (c >= C) return;
    const int R = BB / NSLI;     // 128
    const float* p = z + (size_t)s * R * C + c;
    float sum = 0.0f, sq = 0.0f;
#pragma unroll 4
    for (int r = 0; r < R; ++r) {
        float v = p[(size_t)r * C];
        sum += v;
        sq = fmaf(v, v, sq);
    }
    g_psum[s * 512 + c] = sum;
    g_psq [s * 512 + c] = sq;
}

// phase2: one block reduces NSLI partials per channel (fp64, deterministic)
__global__ void __launch_bounds__(512)
stats2_kernel(int C) {
    const int c = threadIdx.x;
    if (c >= C) return;
    double s = 0.0, q = 0.0;
#pragma unroll
    for (int i = 0; i < NSLI; ++i) {
        s += (double)g_psum[i * 512 + c];
        q += (double)g_psq [i * 512 + c];
    }
    float mu = (float)(s / (double)BB);
    g_mean[c] = mu;
    g_var[c]  = (float)(q / (double)BB - (double)mu * (double)mu);
}

// ======================= downstream ========================================
__global__ void __launch_bounds__(256)
term_kernel(const float* __restrict__ in, int inStride,
            const float* __restrict__ termW, const float* __restrict__ termb,
            int off, int n, float* __restrict__ z) {
    const int t = blockIdx.y;
    __shared__ float Ws[144];
    __shared__ float bs[6];
    if (threadIdx.x < 144) Ws[threadIdx.x] = termW[(size_t)(off + t) * 144 + threadIdx.x];
    if (threadIdx.x < 6)   bs[threadIdx.x] = termb[(size_t)(off + t) * 6 + threadIdx.x];
    __syncthreads();
    const int b = blockIdx.x * blockDim.x + threadIdx.x;
    if (b >= BB) return;
    float xin[24];
    const float* ip = in + (size_t)b * inStride + t * 24;
#pragma unroll
    for (int i = 0; i < 24; i += 4) *(float4*)&xin[i] = *(const float4*)&ip[i];
    const int C = n * 6;
#pragma unroll
    for (int h = 0; h < 6; h++) {
        float s = bs[h];
#pragma unroll
        for (int i = 0; i < 24; i++) s = fmaf(xin[i], Ws[h * 24 + i], s);
        z[(size_t)b * C + t * 6 + h] = tanhf(s);
    }
}

__global__ void __launch_bounds__(256)
bnaux_kernel(float* __restrict__ zh,
             const float* __restrict__ gamma, const float* __restrict__ beta,
             const float* __restrict__ a1W, const float* __restrict__ a1b,
             const float* __restrict__ a2W, const float* __restrict__ a2b,
             int off, int n, int colOff, float* __restrict__ out) {
    const int t = blockIdx.y;
    const int b = blockIdx.x * blockDim.x + threadIdx.x;
    if (b >= BB) return;
    const int C = n * 6;
    float a = a1b[off + t];
#pragma unroll
    for (int k = 0; k < 6; k++) {
        const int c = t * 6 + k;
        float v = zh[(size_t)b * C + c];
        float hv = (v - g_mean[c]) * rsqrtf(g_var[c] + EPSB) * gamma[(size_t)(off + t) * 6 + k]
                   + beta[(size_t)(off + t) * 6 + k];
        zh[(size_t)b * C + c] = hv;
        a = fmaf(hv, a1W[(size_t)(off + t) * 6 + k], a);
    }
    float a1 = tanhf(a);
    out[(size_t)b * OUTC + colOff + t] = fmaf(a1, a2W[off + t], a2b[off + t]);
}

__global__ void __launch_bounds__(256)
final1_kernel(const float* __restrict__ fW, const float* __restrict__ fb) {
    const int b = blockIdx.x * blockDim.x + threadIdx.x;
    if (b >= BB) return;
    float r[6];
#pragma unroll
    for (int i = 0; i < 6; i++) r[i] = g_h3[(size_t)b * 6 + i];
#pragma unroll
    for (int o = 0; o < 6; o++) {
        float s = fb[o];
#pragma unroll
        for (int i = 0; i < 6; i++) s = fmaf(r[i], fW[o * 6 + i], s);
        g_f[(size_t)b * 6 + o] = tanhf(s);
    }
}

__global__ void __launch_bounds__(256)
final2_kernel(const float* __restrict__ fg, const float* __restrict__ fbta,
              const float* __restrict__ fauxW, const float* __restrict__ fauxb,
              const float* __restrict__ foutW, const float* __restrict__ foutb,
              float* __restrict__ out) {
    const int b = blockIdx.x * blockDim.x + threadIdx.x;
    if (b >= BB) return;
    float a = fauxb[0];
#pragma unroll
    for (int h = 0; h < 6; h++) {
        float v = (g_f[(size_t)b * 6 + h] - g_mean[h]) * rsqrtf(g_var[h] + EPSB) * fg[h] + fbta[h];
        a = fmaf(v, fauxW[h], a);
    }
    float fa = tanhf(a);
    float p = fmaf(fa, foutW[0], foutb[0]);
    out[(size_t)b * OUTC + 85] = 1.0f / (1.0f + expf(-p));
}

// ---------------------------------------------------------------------------
extern "C" void kernel_launch(void* const* d_in, const int* in_sizes, int n_in,
                              void* d_out, int out_size) {
    (void)in_sizes; (void)n_in; (void)out_size;
    const float* x      = (const float*)d_in[0];
    const float* geneW  = (const float*)d_in[1];
    const float* geneb  = (const float*)d_in[2];
    const float* termW  = (const float*)d_in[3];
    const float* termb  = (const float*)d_in[4];
    const float* bng    = (const float*)d_in[5];
    const float* bnb    = (const float*)d_in[6];
    const float* a1W    = (const float*)d_in[7];
    const float* a1b    = (const float*)d_in[8];
    const float* a2W    = (const float*)d_in[9];
    const float* a2b    = (const float*)d_in[10];
    const float* finalW = (const float*)d_in[11];
    const float* finalb = (const float*)d_in[12];
    const float* fbng   = (const float*)d_in[13];
    const float* fbnb   = (const float*)d_in[14];
    const float* fauxW  = (const float*)d_in[15];
    const float* fauxb  = (const float*)d_in[16];
    const float* foutW  = (const float*)d_in[17];
    const float* foutb  = (const float*)d_in[18];
    float* out = (float*)d_out;

    float *h0, *h1, *h2, *h3, *f, *beff;
    __nv_bfloat16 *xhi, *xlo, *whi, *wlo;
    cudaGetSymbolAddress((void**)&h0, g_h0);
    cudaGetSymbolAddress((void**)&h1, g_h1);
    cudaGetSymbolAddress((void**)&h2, g_h2);
    cudaGetSymbolAddress((void**)&h3, g_h3);
    cudaGetSymbolAddress((void**)&f, g_f);
    cudaGetSymbolAddress((void**)&xhi, g_xhi);
    cudaGetSymbolAddress((void**)&xlo, g_xlo);
    cudaGetSymbolAddress((void**)&whi, g_weffhi);
    cudaGetSymbolAddress((void**)&wlo, g_wefflo);
    cudaGetSymbolAddress((void**)&beff, g_beff);

    // 0) x split + W_eff precompute (independent)
    split_kernel<<<(BB * GG / 4 + 255) / 256, 256>>>(x, xhi, xlo, BB * GG / 4);
    {
        dim3 g(GG / 256, 64);
        weff_kernel<<<g, 256>>>(geneW, geneb, termW, termb, whi, wlo, beff);
    }

    // 1) fused gene+term0 GEMM -> z level0 (tanh applied)
    {
        cudaFuncSetAttribute(gemm_fused_kernel,
                             cudaFuncAttributeMaxDynamicSharedMemorySize, GEMM_SMEM);
        dim3 grid(NF2 / 64, BB / 64);
        gemm_fused_kernel<<<grid, 128, GEMM_SMEM>>>(xhi, xlo, whi, wlo, beff, h0);
    }

    // 2) level0 BN + aux
    {
        dim3 g1((384 + 255) / 256, NSLI);
        stats1_kernel<<<g1, 256>>>(h0, 384);
        stats2_kernel<<<1, 512>>>(384);
        dim3 gterm(BB / 256, 64);
        bnaux_kernel<<<gterm, 256>>>(h0, bng, bnb, a1W, a1b, a2W, a2b, 0, 64, 0, out);
    }

    // 3) levels 1-3
    const int   lvl_n[3]        = {16, 4, 1};
    const int   lvl_off[3]      = {64, 80, 84};
    const int   lvl_inStride[3] = {384, 96, 24};
    const float* lvl_in[3]      = {h0, h1, h2};
    float*      lvl_z[3]        = {h1, h2, h3};

    for (int l = 0; l < 3; l++) {
        const int n = lvl_n[l], off = lvl_off[l];
        const int C = n * 6;
        dim3 gterm(BB / 256, n);
        term_kernel<<<gterm, 256>>>(lvl_in[l], lvl_inStride[l], termW, termb, off, n, lvl_z[l]);
        dim3 g1((C + 255) / 256, NSLI);
        stats1_kernel<<<g1, 256>>>(lvl_z[l], C);
        stats2_kernel<<<1, 512>>>(C);
        bnaux_kernel<<<gterm, 256>>>(lvl_z[l], bng, bnb, a1W, a1b, a2W, a2b,
                                     off, n, off, out);
    }

    // 4) final head
    final1_kernel<<<BB / 256, 256>>>(finalW, finalb);
    {
        dim3 g1(1, NSLI);
        stats1_kernel<<<g1, 256>>>(f, 6);
        stats2_kernel<<<1, 512>>>(6);
    }
    final2_kernel<<<BB / 256, 256>>>(fbng, fbnb, fauxW, fauxb, foutW, foutb, out);
}